// round 9
// baseline (speedup 1.0000x reference)
#include <cuda_runtime.h>
#include <cuda_bf16.h>
#include <cstdint>

// Problem constants
#define BATCH   2
#define NPTS    2048
#define CIN     64
#define COUT    128
#define GRIDV   12
#define NVOX    (GRIDV*GRIDV*GRIDV)   // 1728
#define NOFF    27
#define NGRP    9                     // offset groups (split-K)
#define OPG     (NOFF/NGRP)           // 3 offsets per group
#define TM      64                    // points per conv block
#define NTILE   (BATCH*NPTS/TM)       // 64 point tiles
#define NROWS   (BATCH*NVOX)          // 3456
#define ZROW    NROWS                 // dedicated zero row index
#define OUTN    (BATCH*NPTS*COUT)     // 524288

// Scratch (device globals; no allocation allowed)
__device__ float g_aggF[NROWS * CIN];
__device__ __align__(16) unsigned char g_aggH[(NROWS + 1) * 128];  // bf16 hi rows (+zero row)
__device__ __align__(16) unsigned char g_aggL[(NROWS + 1) * 128];  // bf16 lo rows
// W per offset: 32KB contiguous = [h][n][128B row], SW128-PRE-SWIZZLED within each 16KB half
__device__ __align__(1024) unsigned char g_Wn[NOFF * 32768];
// split-K partial outputs
__device__ float g_part[NGRP * OUTN];

// ---------------------------------------------------------------------------
// Helpers
// ---------------------------------------------------------------------------
#define CP_ASYNC16(dst_u32, src_ptr) \
    asm volatile("cp.async.cg.shared.global [%0], [%1], 16;" :: "r"(dst_u32), "l"(src_ptr))
#define CP_ASYNC_COMMIT() asm volatile("cp.async.commit_group;" ::: "memory")
#define CP_ASYNC_WAIT0()  asm volatile("cp.async.wait_group 0;" ::: "memory")

#define MBAR_INIT(a, c) \
    asm volatile("mbarrier.init.shared.b64 [%0], %1;" :: "r"(a), "r"(c) : "memory")
#define MBAR_EXPECT_TX(a, b) \
    asm volatile("mbarrier.arrive.expect_tx.shared.b64 _, [%0], %1;" :: "r"(a), "r"(b) : "memory")
#define BULK_G2S(dst, src, bytes, mbar) \
    asm volatile("cp.async.bulk.shared::cluster.global.mbarrier::complete_tx::bytes [%0], [%1], %2, [%3];" \
                 :: "r"(dst), "l"(src), "r"(bytes), "r"(mbar) : "memory")

__device__ __forceinline__ void mbar_wait_parity(uint32_t mbar, uint32_t parity) {
    asm volatile(
        "{\n\t.reg .pred P;\n\t"
        "WL_%=:\n\t"
        "mbarrier.try_wait.parity.acquire.cta.shared::cta.b64 P, [%0], %1, 0x989680;\n\t"
        "@!P bra WL_%=;\n\t}"
        :: "r"(mbar), "r"(parity) : "memory");
}

__device__ __forceinline__ uint32_t smem_u32(const void* p) {
    uint32_t a;
    asm("{ .reg .u64 t; cvta.to.shared.u64 t, %1; cvt.u32.u64 %0, t; }" : "=r"(a) : "l"(p));
    return a;
}

__device__ __forceinline__ void ldsm_x4(uint32_t* r, uint32_t addr) {
    asm volatile("ldmatrix.sync.aligned.m8n8.x4.shared.b16 {%0,%1,%2,%3}, [%4];"
                 : "=r"(r[0]), "=r"(r[1]), "=r"(r[2]), "=r"(r[3]) : "r"(addr));
}

__device__ __forceinline__ void mma_bf16(float* c, const uint32_t* a, uint32_t b0, uint32_t b1) {
    asm volatile(
        "mma.sync.aligned.m16n8k16.row.col.f32.bf16.bf16.f32 "
        "{%0,%1,%2,%3}, {%4,%5,%6,%7}, {%8,%9}, {%0,%1,%2,%3};"
        : "+f"(c[0]), "+f"(c[1]), "+f"(c[2]), "+f"(c[3])
        : "r"(a[0]), "r"(a[1]), "r"(a[2]), "r"(a[3]), "r"(b0), "r"(b1));
}

__device__ __forceinline__ uint32_t pack_hi(float f0, float f1) {
    return ((uint32_t)__bfloat16_as_ushort(__float2bfloat16(f1)) << 16)
         | __bfloat16_as_ushort(__float2bfloat16(f0));
}
__device__ __forceinline__ uint32_t pack_lo(float f0, float f1) {
    float r0 = f0 - __bfloat162float(__float2bfloat16(f0));
    float r1 = f1 - __bfloat162float(__float2bfloat16(f1));
    return ((uint32_t)__bfloat16_as_ushort(__float2bfloat16(r1)) << 16)
         | __bfloat16_as_ushort(__float2bfloat16(r0));
}

// ---------------------------------------------------------------------------
// Kernel 1: zero aggF + pack W (n-major bf16 hi/lo, SW128 pre-swizzled)
// ---------------------------------------------------------------------------
__global__ void prep_kernel(const float* __restrict__ weight) {
    int bid = blockIdx.x;
    if (bid < 216) {
        int t = bid * 256 + threadIdx.x;
        ((float4*)g_aggF)[t] = make_float4(0.f, 0.f, 0.f, 0.f);
    } else {
        int i = (bid - 216) * 256 + threadIdx.x;   // 0..221183
        int n  = i & 127;
        int k2 = (i >> 7) & 31;
        int h  = (i >> 12) & 1;
        int o  = i >> 13;                          // 0..26
        float w0 = weight[(o * CIN + 2 * k2) * COUT + n];
        float w1 = weight[(o * CIN + 2 * k2 + 1) * COUT + n];
        uint32_t pk = (h == 0) ? pack_hi(w0, w1) : pack_lo(w0, w1);
        // SW128 swizzle: within a 16KB half, chunk bits[6:4] ^= (n&7)
        uint32_t off = (uint32_t)n * 128 + (((uint32_t)k2 * 4) ^ (((uint32_t)n & 7) << 4));
        *(uint32_t*)(g_Wn + (size_t)(o * 2 + h) * 16384 + off) = pk;
    }
}

// ---------------------------------------------------------------------------
// Kernel 2: scatter-add features into per-voxel bins
// ---------------------------------------------------------------------------
__global__ void aggregate_kernel(const float* __restrict__ points,
                                 const float* __restrict__ feats) {
    int gid = blockIdx.x * blockDim.x + threadIdx.x;
    if (gid >= BATCH * NPTS * CIN) return;
    int c = gid & (CIN - 1);
    int p = gid >> 6;
    int b = p / NPTS;
    int vx = (int)points[p * 3 + 0];
    int vy = (int)points[p * 3 + 1];
    int vz = (int)points[p * 3 + 2];
    if ((unsigned)vx >= GRIDV || (unsigned)vy >= GRIDV || (unsigned)vz >= GRIDV) return;
    int lin = (vx * GRIDV + vy) * GRIDV + vz;
    atomicAdd(&g_aggF[(b * NVOX + lin) * CIN + c], feats[gid]);
}

// ---------------------------------------------------------------------------
// Kernel 3: convert aggF -> bf16 hi/lo rows (once per voxel), plus zero row
// ---------------------------------------------------------------------------
__global__ void convert_kernel() {
    int gid = blockIdx.x * blockDim.x + threadIdx.x;
    if (gid >= (NROWS + 1) * 32) return;
    int row = gid >> 5;
    int c2  = gid & 31;
    uint32_t hp = 0, lp = 0;
    if (row < NROWS) {
        float2 v = *(const float2*)(g_aggF + (size_t)row * CIN + c2 * 2);
        hp = pack_hi(v.x, v.y);
        lp = pack_lo(v.x, v.y);
    }
    *(uint32_t*)(g_aggH + (size_t)row * 128 + c2 * 4) = hp;
    *(uint32_t*)(g_aggL + (size_t)row * 128 + c2 * 4) = lp;
}

// ---------------------------------------------------------------------------
// Kernel 4: split-K mma.sync conv. grid = NGRP*NTILE = 576 blocks, 128 thr.
// Tile 64 points x 128 couts over offsets [g*3, g*3+3) -> g_part[g].
// 4 warps, warp tile 32 x 64: wm = warp>>1 (rows wm*32+32), wn = warp&1.
// Per kk: 12 ldsm.x4 feed 48 mma (2x less smem read per MAC than before).
// ---------------------------------------------------------------------------
#define RSTR   144
#define WBUF   32768                   // per-offset W (hi 16K | lo 16K)
#define ABUF   (2 * TM * RSTR)         // 18432 (hi block | lo block)
#define SMO_W  0
#define SMO_A  (2 * WBUF)              // 65536
#define SMO_VOX (SMO_A + 2 * ABUF)     // 102400
#define SMO_MBAR (SMO_VOX + 3 * TM * 4)  // 103168
#define SMEM_TOTAL (SMO_MBAR + 64)     // 103232

__global__ __launch_bounds__(128, 2)
void conv_mma_kernel(const float* __restrict__ points) {
    extern __shared__ __align__(1024) unsigned char smem[];
    int* svox = (int*)(smem + SMO_VOX);

    const int tid  = threadIdx.x;
    const int warp = tid >> 5;
    const int lane = tid & 31;
    const int wm   = warp >> 1;      // 0..1 : rows [wm*32, +32)
    const int wn   = warp & 1;       // 0..1 : couts [wn*64, +64)
    const int grp  = lane >> 2;      // 0..7
    const int tig  = lane & 3;       // 0..3

    const int g    = blockIdx.x >> 6;        // offset group 0..8
    const int tile = blockIdx.x & 63;        // point tile
    const int o0   = g * OPG;
    const int p0   = tile * TM;
    const int b    = p0 >> 11;       // / NPTS

    if (tid < TM) {
        int p = p0 + tid;
        svox[tid]          = (int)points[p * 3 + 0];
        svox[TM + tid]     = (int)points[p * 3 + 1];
        svox[2 * TM + tid] = (int)points[p * 3 + 2];
    }
    __syncthreads();

    const uint32_t sb = smem_u32(smem);
    const uint32_t mbar0 = sb + SMO_MBAR;
    const uint32_t mbar1 = sb + SMO_MBAR + 8;

    if (tid == 0) {
        MBAR_INIT(mbar0, 1);
        MBAR_INIT(mbar1, 1);
    }
    __syncthreads();

    // ---- A staging: 8 cp.async per thread (row = tid>>1, half = tid&1) ----
    const int arow = tid >> 1;           // 0..63
    const int aq   = tid & 1;            // 0..1 -> bytes [aq*64, +64)
    const int avx = svox[arow], avy = svox[TM + arow], avz = svox[2 * TM + arow];

    auto issueA = [&](int o, int bi) {
        int dx = o / 9 - 1, dy = (o / 3) % 3 - 1, dz = o % 3 - 1;
        int nx = avx + dx, ny = avy + dy, nz = avz + dz;
        int rowIdx = ZROW;
        if ((unsigned)nx < GRIDV && (unsigned)ny < GRIDV && (unsigned)nz < GRIDV)
            rowIdx = b * NVOX + (nx * GRIDV + ny) * GRIDV + nz;
        const unsigned char* srcH = g_aggH + (size_t)rowIdx * 128 + aq * 64;
        const unsigned char* srcL = g_aggL + (size_t)rowIdx * 128 + aq * 64;
        uint32_t dstH = sb + SMO_A + bi * ABUF + arow * RSTR + aq * 64;
        uint32_t dstL = dstH + TM * RSTR;
        #pragma unroll
        for (int q = 0; q < 4; q++) {
            CP_ASYNC16(dstH + q * 16, srcH + q * 16);
            CP_ASYNC16(dstL + q * 16, srcL + q * 16);
        }
    };

    float c[64];
    #pragma unroll
    for (int i = 0; i < 64; i++) c[i] = 0.f;

    // ---- prologue: W0 bulk + A0 ----
    if (tid == 0) {
        MBAR_EXPECT_TX(mbar0, WBUF);
        BULK_G2S(sb + SMO_W, g_Wn + (size_t)o0 * WBUF, WBUF, mbar0);
    }
    issueA(o0, 0);
    CP_ASYNC_COMMIT();
    mbar_wait_parity(mbar0, 0);
    CP_ASYNC_WAIT0();
    __syncthreads();
    uint32_t ph0 = 1, ph1 = 0;   // next expected parity per buffer

    // ---- ldmatrix lane addressing ----
    // A (144B rows, no swizzle): row = wm*32 + mb*16 + ((lane>>3)&1)*8 + (lane&7)
    const uint32_t aAddrBase = sb + SMO_A
        + (uint32_t)(wm * 32 + ((lane >> 3) & 1) * 8 + (lane & 7)) * RSTR
        + ((lane >> 4) & 1) * 16;
    // B (128B rows, SW128): n = wn*64 + j*16 + ((lane>>4)&1)*8 + (lane&7)
    const int bc   = lane & 7;
    const uint32_t bXor = (uint32_t)bc << 4;
    const uint32_t bRow0 = sb + SMO_W
        + (uint32_t)(wn * 64 + ((lane >> 4) & 1) * 8 + bc) * 128;
    const uint32_t bKsel = ((lane >> 3) & 1) * 16;

    for (int oo = 0; oo < OPG; oo++) {
        const int cur = oo & 1;
        const int nxt = cur ^ 1;
        const bool more = (oo + 1 < OPG);

        if (more) {
            if (tid == 0) {
                uint32_t mb = nxt ? mbar1 : mbar0;
                MBAR_EXPECT_TX(mb, WBUF);
                BULK_G2S(sb + SMO_W + nxt * WBUF,
                         g_Wn + (size_t)(o0 + oo + 1) * WBUF, WBUF, mb);
            }
            issueA(o0 + oo + 1, nxt);
            CP_ASYNC_COMMIT();
        }

        // ---- fused 3-pass mma over 4 k-steps, warp tile 32x64 ----
        const uint32_t aH = aAddrBase + (uint32_t)cur * ABUF;
        const uint32_t aL = aH + TM * RSTR;
        const uint32_t bH = bRow0 + (uint32_t)cur * WBUF;
        const uint32_t bL = bH + 16384;
        #pragma unroll
        for (int kk = 0; kk < 4; kk++) {
            const uint32_t kx = ((uint32_t)(kk * 32) + bKsel) ^ bXor;
            uint32_t ah[2][4], al[2][4];
            #pragma unroll
            for (int mb = 0; mb < 2; mb++) {
                ldsm_x4(ah[mb], aH + mb * (16 * RSTR) + kk * 32);
                ldsm_x4(al[mb], aL + mb * (16 * RSTR) + kk * 32);
            }
            #pragma unroll
            for (int j = 0; j < 4; j++) {
                uint32_t bh[4], bl[4];
                ldsm_x4(bh, bH + j * 2048 + kx);
                ldsm_x4(bl, bL + j * 2048 + kx);
                #pragma unroll
                for (int mb = 0; mb < 2; mb++) {
                    float* c0 = &c[(mb * 8 + 2 * j) * 4];
                    float* c1 = c0 + 4;
                    mma_bf16(c0, ah[mb], bh[0], bh[1]);   // Ah*Wh
                    mma_bf16(c1, ah[mb], bh[2], bh[3]);
                    mma_bf16(c0, ah[mb], bl[0], bl[1]);   // Ah*Wl
                    mma_bf16(c1, ah[mb], bl[2], bl[3]);
                    mma_bf16(c0, al[mb], bh[0], bh[1]);   // Al*Wh
                    mma_bf16(c1, al[mb], bh[2], bh[3]);
                }
            }
        }

        if (more) {
            if (nxt == 0) { mbar_wait_parity(mbar0, ph0); ph0 ^= 1; }
            else         { mbar_wait_parity(mbar1, ph1); ph1 ^= 1; }
            CP_ASYNC_WAIT0();
        }
        __syncthreads();
    }

    // ---- epilogue: write partial (no bias here) ----
    float* pout = g_part + (size_t)g * OUTN;
    #pragma unroll
    for (int mb = 0; mb < 2; mb++) {
        const int r0 = p0 + wm * 32 + mb * 16 + grp;
        #pragma unroll
        for (int f = 0; f < 8; f++) {
            int col = wn * 64 + f * 8 + tig * 2;
            const float* cc = &c[(mb * 8 + f) * 4];
            *(float2*)(pout + (size_t)r0 * COUT + col)       = make_float2(cc[0], cc[1]);
            *(float2*)(pout + (size_t)(r0 + 8) * COUT + col) = make_float2(cc[2], cc[3]);
        }
    }
}

// ---------------------------------------------------------------------------
// Kernel 5: reduce partials + bias -> out
// ---------------------------------------------------------------------------
__global__ void reduce_kernel(const float* __restrict__ bias, float* __restrict__ out) {
    int i = blockIdx.x * blockDim.x + threadIdx.x;   // float4 index, < OUTN/4
    if (i >= OUTN / 4) return;
    float4 bv = ((const float4*)bias)[i & 31];
    float4 r = bv;
    #pragma unroll
    for (int g = 0; g < NGRP; g++) {
        float4 v = ((const float4*)(g_part + (size_t)g * OUTN))[i];
        r.x += v.x; r.y += v.y; r.z += v.z; r.w += v.w;
    }
    ((float4*)out)[i] = r;
}

// ---------------------------------------------------------------------------
extern "C" void kernel_launch(void* const* d_in, const int* in_sizes, int n_in,
                              void* d_out, int out_size) {
    const float* points  = (const float*)d_in[0];   // (B, N, 3)
    const float* feats   = (const float*)d_in[1];   // (B, N, CIN)
    const float* weight  = (const float*)d_in[2];   // (3,3,3,CIN,COUT)
    const float* bias    = (const float*)d_in[3];   // (COUT)
    float* out = (float*)d_out;                     // (B, N, COUT)

    cudaFuncSetAttribute(conv_mma_kernel,
                         cudaFuncAttributeMaxDynamicSharedMemorySize, SMEM_TOTAL);

    // 1) zero agg scratch + pack W (swizzled n-major bf16 hi/lo)
    prep_kernel<<<1080, 256>>>(weight);
    // 2) per-voxel feature aggregation (fp32 atomics)
    aggregate_kernel<<<(BATCH * NPTS * CIN + 255) / 256, 256>>>(points, feats);
    // 3) convert aggF to bf16 hi/lo rows (+ zero row)
    convert_kernel<<<((NROWS + 1) * 32 + 255) / 256, 256>>>();
    // 4) split-K tensor-core conv -> partials (warp tile 32x64)
    conv_mma_kernel<<<NGRP * NTILE, 128, SMEM_TOTAL>>>(points);
    // 5) reduce partials + bias -> out
    reduce_kernel<<<(OUTN / 4 + 255) / 256, 256>>>(bias, out);
}

// round 10
// speedup vs baseline: 1.4953x; 1.4953x over previous
#include <cuda_runtime.h>
#include <cuda_fp16.h>
#include <cstdint>

// Problem constants
#define BATCH   2
#define NPTS    2048
#define CIN     64
#define COUT    128
#define GRIDV   12
#define NVOX    (GRIDV*GRIDV*GRIDV)   // 1728
#define NOFF    27
#define NGRP    3                     // offset groups (split-K)
#define OPG     (NOFF/NGRP)           // 9 offsets per group
#define TM      64                    // points per conv block
#define NTILE   (BATCH*NPTS/TM)       // 64 point tiles
#define NROWS   (BATCH*NVOX)          // 3456
#define ZROW    NROWS                 // dedicated zero row index
#define OUTN    (BATCH*NPTS*COUT)     // 524288

// Scratch (device globals; no allocation allowed)
__device__ float g_aggF[NROWS * CIN];
__device__ __align__(16) unsigned char g_aggH[(NROWS + 1) * 128];  // fp16 hi rows (+zero row)
__device__ __align__(16) unsigned char g_aggL[(NROWS + 1) * 128];  // fp16 lo rows
// W per offset: 16KB = [n][128B row], fp16, SW128-PRE-SWIZZLED
__device__ __align__(1024) unsigned char g_Wn[NOFF * 16384];

// ---------------------------------------------------------------------------
// Helpers
// ---------------------------------------------------------------------------
#define CP_ASYNC16(dst_u32, src_ptr) \
    asm volatile("cp.async.cg.shared.global [%0], [%1], 16;" :: "r"(dst_u32), "l"(src_ptr))
#define CP_ASYNC_COMMIT() asm volatile("cp.async.commit_group;" ::: "memory")
#define CP_ASYNC_WAIT0()  asm volatile("cp.async.wait_group 0;" ::: "memory")

#define MBAR_INIT(a, c) \
    asm volatile("mbarrier.init.shared.b64 [%0], %1;" :: "r"(a), "r"(c) : "memory")
#define MBAR_EXPECT_TX(a, b) \
    asm volatile("mbarrier.arrive.expect_tx.shared.b64 _, [%0], %1;" :: "r"(a), "r"(b) : "memory")
#define BULK_G2S(dst, src, bytes, mbar) \
    asm volatile("cp.async.bulk.shared::cluster.global.mbarrier::complete_tx::bytes [%0], [%1], %2, [%3];" \
                 :: "r"(dst), "l"(src), "r"(bytes), "r"(mbar) : "memory")

__device__ __forceinline__ void mbar_wait_parity(uint32_t mbar, uint32_t parity) {
    asm volatile(
        "{\n\t.reg .pred P;\n\t"
        "WL_%=:\n\t"
        "mbarrier.try_wait.parity.acquire.cta.shared::cta.b64 P, [%0], %1, 0x989680;\n\t"
        "@!P bra WL_%=;\n\t}"
        :: "r"(mbar), "r"(parity) : "memory");
}

__device__ __forceinline__ uint32_t smem_u32(const void* p) {
    uint32_t a;
    asm("{ .reg .u64 t; cvta.to.shared.u64 t, %1; cvt.u32.u64 %0, t; }" : "=r"(a) : "l"(p));
    return a;
}

__device__ __forceinline__ void ldsm_x4(uint32_t* r, uint32_t addr) {
    asm volatile("ldmatrix.sync.aligned.m8n8.x4.shared.b16 {%0,%1,%2,%3}, [%4];"
                 : "=r"(r[0]), "=r"(r[1]), "=r"(r[2]), "=r"(r[3]) : "r"(addr));
}

__device__ __forceinline__ void mma_f16(float* c, const uint32_t* a, uint32_t b0, uint32_t b1) {
    asm volatile(
        "mma.sync.aligned.m16n8k16.row.col.f32.f16.f16.f32 "
        "{%0,%1,%2,%3}, {%4,%5,%6,%7}, {%8,%9}, {%0,%1,%2,%3};"
        : "+f"(c[0]), "+f"(c[1]), "+f"(c[2]), "+f"(c[3])
        : "r"(a[0]), "r"(a[1]), "r"(a[2]), "r"(a[3]), "r"(b0), "r"(b1));
}

__device__ __forceinline__ uint32_t pack_h(float f0, float f1) {
    __half h0 = __float2half(f0), h1 = __float2half(f1);
    return ((uint32_t)__half_as_ushort(h1) << 16) | __half_as_ushort(h0);
}
__device__ __forceinline__ uint32_t pack_l(float f0, float f1) {
    float r0 = f0 - __half2float(__float2half(f0));
    float r1 = f1 - __half2float(__float2half(f1));
    return pack_h(r0, r1);
}

// ---------------------------------------------------------------------------
// Kernel 1: zero aggF + pack W (fp16, SW128 pre-swizzled) + out = bias
// blocks [0,216): zero aggF; [216,648): W pack; [648,1160): bias init
// ---------------------------------------------------------------------------
__global__ void prep_kernel(const float* __restrict__ weight,
                            const float* __restrict__ bias,
                            float* __restrict__ out) {
    int bid = blockIdx.x;
    if (bid < 216) {
        int t = bid * 256 + threadIdx.x;
        ((float4*)g_aggF)[t] = make_float4(0.f, 0.f, 0.f, 0.f);
    } else if (bid < 648) {
        int i = (bid - 216) * 256 + threadIdx.x;   // 0..110591
        int n  = i & 127;
        int k2 = (i >> 7) & 31;
        int o  = i >> 12;                          // 0..26
        float w0 = weight[(o * CIN + 2 * k2) * COUT + n];
        float w1 = weight[(o * CIN + 2 * k2 + 1) * COUT + n];
        // SW128 swizzle: chunk bits[6:4] ^= (n&7)
        uint32_t off = (uint32_t)n * 128 + (((uint32_t)k2 * 4) ^ (((uint32_t)n & 7) << 4));
        *(uint32_t*)(g_Wn + (size_t)o * 16384 + off) = pack_h(w0, w1);
    } else {
        int i = (bid - 648) * 256 + threadIdx.x;   // float4 idx < OUTN/4 = 131072
        ((float4*)out)[i] = ((const float4*)bias)[i & 31];
    }
}

// ---------------------------------------------------------------------------
// Kernel 2: scatter-add features into per-voxel bins
// ---------------------------------------------------------------------------
__global__ void aggregate_kernel(const float* __restrict__ points,
                                 const float* __restrict__ feats) {
    int gid = blockIdx.x * blockDim.x + threadIdx.x;
    if (gid >= BATCH * NPTS * CIN) return;
    int c = gid & (CIN - 1);
    int p = gid >> 6;
    int b = p / NPTS;
    int vx = (int)points[p * 3 + 0];
    int vy = (int)points[p * 3 + 1];
    int vz = (int)points[p * 3 + 2];
    if ((unsigned)vx >= GRIDV || (unsigned)vy >= GRIDV || (unsigned)vz >= GRIDV) return;
    int lin = (vx * GRIDV + vy) * GRIDV + vz;
    atomicAdd(&g_aggF[(b * NVOX + lin) * CIN + c], feats[gid]);
}

// ---------------------------------------------------------------------------
// Kernel 3: convert aggF -> fp16 hi/lo rows (once per voxel), plus zero row
// ---------------------------------------------------------------------------
__global__ void convert_kernel() {
    int gid = blockIdx.x * blockDim.x + threadIdx.x;
    if (gid >= (NROWS + 1) * 32) return;
    int row = gid >> 5;
    int c2  = gid & 31;
    uint32_t hp = 0, lp = 0;
    if (row < NROWS) {
        float2 v = *(const float2*)(g_aggF + (size_t)row * CIN + c2 * 2);
        hp = pack_h(v.x, v.y);
        lp = pack_l(v.x, v.y);
    }
    *(uint32_t*)(g_aggH + (size_t)row * 128 + c2 * 4) = hp;
    *(uint32_t*)(g_aggL + (size_t)row * 128 + c2 * 4) = lp;
}

// ---------------------------------------------------------------------------
// Kernel 4: split-K fp16 mma conv. grid = NTILE*NGRP = 192 blocks, 256 thr.
// Tile 64 points x 128 couts over offsets [g*9, +9). 2-pass: Ah*W + Al*W.
// Warp (wm 0..3, wn 0..1): 16 rows x 64 couts. Epilogue atomicAdd into out.
// ---------------------------------------------------------------------------
#define RSTR   144
#define WBUF   16384                   // per-offset W (fp16)
#define ABUF   (2 * TM * RSTR)         // 18432 (hi block | lo block)
#define SMO_W  0
#define SMO_A  (2 * WBUF)              // 32768
#define SMO_VOX (SMO_A + 2 * ABUF)     // 69632
#define SMO_MBAR (SMO_VOX + 3 * TM * 4)  // 70400
#define SMEM_TOTAL (SMO_MBAR + 64)     // 70464

__global__ __launch_bounds__(256, 2)
void conv_mma_kernel(const float* __restrict__ points, float* __restrict__ out) {
    extern __shared__ __align__(1024) unsigned char smem[];
    int* svox = (int*)(smem + SMO_VOX);

    const int tid  = threadIdx.x;
    const int warp = tid >> 5;
    const int lane = tid & 31;
    const int wm   = warp >> 1;      // 0..3 : rows [wm*16, +16)
    const int wn   = warp & 1;       // 0..1 : couts [wn*64, +64)
    const int grp  = lane >> 2;      // 0..7
    const int tig  = lane & 3;       // 0..3

    const int g    = blockIdx.x % NGRP;      // offset group
    const int tile = blockIdx.x / NGRP;      // point tile
    const int o0   = g * OPG;
    const int p0   = tile * TM;
    const int b    = p0 >> 11;       // / NPTS

    if (tid < TM) {
        int p = p0 + tid;
        svox[tid]          = (int)points[p * 3 + 0];
        svox[TM + tid]     = (int)points[p * 3 + 1];
        svox[2 * TM + tid] = (int)points[p * 3 + 2];
    }
    __syncthreads();

    const uint32_t sb = smem_u32(smem);
    const uint32_t mbar0 = sb + SMO_MBAR;
    const uint32_t mbar1 = sb + SMO_MBAR + 8;

    if (tid == 0) {
        MBAR_INIT(mbar0, 1);
        MBAR_INIT(mbar1, 1);
    }
    __syncthreads();

    // ---- A staging: 4 cp.async per thread (row = tid>>2, quarter = tid&3) ----
    const int arow = tid >> 2;           // 0..63
    const int aq   = tid & 3;            // 0..3 -> bytes [aq*32, +32)
    const int avx = svox[arow], avy = svox[TM + arow], avz = svox[2 * TM + arow];

    auto issueA = [&](int o, int bi) {
        int dx = o / 9 - 1, dy = (o / 3) % 3 - 1, dz = o % 3 - 1;
        int nx = avx + dx, ny = avy + dy, nz = avz + dz;
        int rowIdx = ZROW;
        if ((unsigned)nx < GRIDV && (unsigned)ny < GRIDV && (unsigned)nz < GRIDV)
            rowIdx = b * NVOX + (nx * GRIDV + ny) * GRIDV + nz;
        const unsigned char* srcH = g_aggH + (size_t)rowIdx * 128 + aq * 32;
        const unsigned char* srcL = g_aggL + (size_t)rowIdx * 128 + aq * 32;
        uint32_t dstH = sb + SMO_A + bi * ABUF + arow * RSTR + aq * 32;
        uint32_t dstL = dstH + TM * RSTR;
        CP_ASYNC16(dstH,      srcH);
        CP_ASYNC16(dstH + 16, srcH + 16);
        CP_ASYNC16(dstL,      srcL);
        CP_ASYNC16(dstL + 16, srcL + 16);
    };

    float c[32];
    #pragma unroll
    for (int i = 0; i < 32; i++) c[i] = 0.f;

    // ---- prologue: W0 bulk + A0 ----
    if (tid == 0) {
        MBAR_EXPECT_TX(mbar0, WBUF);
        BULK_G2S(sb + SMO_W, g_Wn + (size_t)o0 * WBUF, WBUF, mbar0);
    }
    issueA(o0, 0);
    CP_ASYNC_COMMIT();
    mbar_wait_parity(mbar0, 0);
    CP_ASYNC_WAIT0();
    __syncthreads();
    uint32_t ph0 = 1, ph1 = 0;   // next expected parity per buffer

    // ---- ldmatrix lane addressing ----
    // A (144B rows, no swizzle)
    const uint32_t aAddrBase = sb + SMO_A
        + (uint32_t)(wm * 16 + ((lane >> 3) & 1) * 8 + (lane & 7)) * RSTR
        + ((lane >> 4) & 1) * 16;
    // B (128B rows, SW128)
    const int bc   = lane & 7;
    const uint32_t bXor = (uint32_t)bc << 4;
    const uint32_t bRow0 = sb + SMO_W
        + (uint32_t)(wn * 64 + ((lane >> 4) & 1) * 8 + bc) * 128;
    const uint32_t bKsel = ((lane >> 3) & 1) * 16;

    for (int oo = 0; oo < OPG; oo++) {
        const int cur = oo & 1;
        const int nxt = cur ^ 1;
        const bool more = (oo + 1 < OPG);

        if (more) {
            if (tid == 0) {
                uint32_t mb = nxt ? mbar1 : mbar0;
                MBAR_EXPECT_TX(mb, WBUF);
                BULK_G2S(sb + SMO_W + nxt * WBUF,
                         g_Wn + (size_t)(o0 + oo + 1) * WBUF, WBUF, mb);
            }
            issueA(o0 + oo + 1, nxt);
            CP_ASYNC_COMMIT();
        }

        // ---- 2-pass mma over 4 k-steps ----
        const uint32_t aH = aAddrBase + (uint32_t)cur * ABUF;
        const uint32_t aL = aH + TM * RSTR;
        const uint32_t bB = bRow0 + (uint32_t)cur * WBUF;
        #pragma unroll
        for (int kk = 0; kk < 4; kk++) {
            const uint32_t kx = ((uint32_t)(kk * 32) + bKsel) ^ bXor;
            uint32_t ah[4], al[4];
            ldsm_x4(ah, aH + kk * 32);
            ldsm_x4(al, aL + kk * 32);
            #pragma unroll
            for (int j = 0; j < 4; j++) {
                uint32_t bh[4];
                ldsm_x4(bh, bB + j * 2048 + kx);
                float* c0 = &c[(2 * j) * 4];
                float* c1 = c0 + 4;
                mma_f16(c0, ah, bh[0], bh[1]);   // Ah*W
                mma_f16(c1, ah, bh[2], bh[3]);
                mma_f16(c0, al, bh[0], bh[1]);   // Al*W
                mma_f16(c1, al, bh[2], bh[3]);
            }
        }

        if (more) {
            if (nxt == 0) { mbar_wait_parity(mbar0, ph0); ph0 ^= 1; }
            else         { mbar_wait_parity(mbar1, ph1); ph1 ^= 1; }
            CP_ASYNC_WAIT0();
        }
        __syncthreads();
    }

    // ---- epilogue: atomicAdd partial into bias-initialized out ----
    const int r0 = p0 + wm * 16 + grp;
    #pragma unroll
    for (int f = 0; f < 8; f++) {
        int col = wn * 64 + f * 8 + tig * 2;
        const float* cc = &c[f * 4];
        float* oA = out + (size_t)r0 * COUT + col;
        float* oB = out + (size_t)(r0 + 8) * COUT + col;
        atomicAdd(oA,     cc[0]);
        atomicAdd(oA + 1, cc[1]);
        atomicAdd(oB,     cc[2]);
        atomicAdd(oB + 1, cc[3]);
    }
}

// ---------------------------------------------------------------------------
extern "C" void kernel_launch(void* const* d_in, const int* in_sizes, int n_in,
                              void* d_out, int out_size) {
    const float* points  = (const float*)d_in[0];   // (B, N, 3)
    const float* feats   = (const float*)d_in[1];   // (B, N, CIN)
    const float* weight  = (const float*)d_in[2];   // (3,3,3,CIN,COUT)
    const float* bias    = (const float*)d_in[3];   // (COUT)
    float* out = (float*)d_out;                     // (B, N, COUT)

    cudaFuncSetAttribute(conv_mma_kernel,
                         cudaFuncAttributeMaxDynamicSharedMemorySize, SMEM_TOTAL);

    // 1) zero agg scratch + pack W (fp16 swizzled) + out = bias
    prep_kernel<<<1160, 256>>>(weight, bias, out);
    // 2) per-voxel feature aggregation (fp32 atomics)
    aggregate_kernel<<<(BATCH * NPTS * CIN + 255) / 256, 256>>>(points, feats);
    // 3) convert aggF to fp16 hi/lo rows (+ zero row)
    convert_kernel<<<((NROWS + 1) * 32 + 255) / 256, 256>>>();
    // 4) split-K fp16 2-pass conv, atomic accumulation into out
    conv_mma_kernel<<<NTILE * NGRP, 256, SMEM_TOTAL>>>(points, out);
}

// round 11
// speedup vs baseline: 1.5842x; 1.0594x over previous
#include <cuda_runtime.h>
#include <cuda_fp16.h>
#include <cstdint>

// Problem constants
#define BATCH   2
#define NPTS    2048
#define CIN     64
#define COUT    128
#define GRIDV   12
#define NVOX    (GRIDV*GRIDV*GRIDV)   // 1728
#define NOFF    27
#define NGRP    3                     // offset groups (split-K)
#define OPG     (NOFF/NGRP)           // 9 offsets per group
#define TM      64                    // points per conv block
#define NTILE   (BATCH*NPTS/TM)       // 64 point tiles
#define NROWS   (BATCH*NVOX)          // 3456
#define ZROW    NROWS                 // dedicated zero row index
#define OUTN    (BATCH*NPTS*COUT)     // 524288

// Scratch (device globals; no allocation allowed)
__device__ float g_aggF[NROWS * CIN];
__device__ __align__(16) unsigned char g_aggH[(NROWS + 1) * 128];  // fp16 rows (+zero row)
// W per offset: 16KB = [n][128B row], fp16, SW128-PRE-SWIZZLED
__device__ __align__(1024) unsigned char g_Wn[NOFF * 16384];

// ---------------------------------------------------------------------------
// Helpers
// ---------------------------------------------------------------------------
#define CP_ASYNC16(dst_u32, src_ptr) \
    asm volatile("cp.async.cg.shared.global [%0], [%1], 16;" :: "r"(dst_u32), "l"(src_ptr))
#define CP_ASYNC_COMMIT() asm volatile("cp.async.commit_group;" ::: "memory")
#define CP_ASYNC_WAIT0()  asm volatile("cp.async.wait_group 0;" ::: "memory")

#define MBAR_INIT(a, c) \
    asm volatile("mbarrier.init.shared.b64 [%0], %1;" :: "r"(a), "r"(c) : "memory")
#define MBAR_EXPECT_TX(a, b) \
    asm volatile("mbarrier.arrive.expect_tx.shared.b64 _, [%0], %1;" :: "r"(a), "r"(b) : "memory")
#define BULK_G2S(dst, src, bytes, mbar) \
    asm volatile("cp.async.bulk.shared::cluster.global.mbarrier::complete_tx::bytes [%0], [%1], %2, [%3];" \
                 :: "r"(dst), "l"(src), "r"(bytes), "r"(mbar) : "memory")

__device__ __forceinline__ void mbar_wait_parity(uint32_t mbar, uint32_t parity) {
    asm volatile(
        "{\n\t.reg .pred P;\n\t"
        "WL_%=:\n\t"
        "mbarrier.try_wait.parity.acquire.cta.shared::cta.b64 P, [%0], %1, 0x989680;\n\t"
        "@!P bra WL_%=;\n\t}"
        :: "r"(mbar), "r"(parity) : "memory");
}

__device__ __forceinline__ uint32_t smem_u32(const void* p) {
    uint32_t a;
    asm("{ .reg .u64 t; cvta.to.shared.u64 t, %1; cvt.u32.u64 %0, t; }" : "=r"(a) : "l"(p));
    return a;
}

__device__ __forceinline__ void ldsm_x4(uint32_t* r, uint32_t addr) {
    asm volatile("ldmatrix.sync.aligned.m8n8.x4.shared.b16 {%0,%1,%2,%3}, [%4];"
                 : "=r"(r[0]), "=r"(r[1]), "=r"(r[2]), "=r"(r[3]) : "r"(addr));
}

__device__ __forceinline__ void mma_f16(float* c, const uint32_t* a, uint32_t b0, uint32_t b1) {
    asm volatile(
        "mma.sync.aligned.m16n8k16.row.col.f32.f16.f16.f32 "
        "{%0,%1,%2,%3}, {%4,%5,%6,%7}, {%8,%9}, {%0,%1,%2,%3};"
        : "+f"(c[0]), "+f"(c[1]), "+f"(c[2]), "+f"(c[3])
        : "r"(a[0]), "r"(a[1]), "r"(a[2]), "r"(a[3]), "r"(b0), "r"(b1));
}

__device__ __forceinline__ uint32_t pack_h(float f0, float f1) {
    __half h0 = __float2half(f0), h1 = __float2half(f1);
    return ((uint32_t)__half_as_ushort(h1) << 16) | __half_as_ushort(h0);
}

// ---------------------------------------------------------------------------
// Kernel 1: zero aggF + pack W (fp16, SW128 pre-swizzled) + out = bias
// blocks [0,216): zero aggF; [216,648): W pack; [648,1160): bias init
// ---------------------------------------------------------------------------
__global__ void prep_kernel(const float* __restrict__ weight,
                            const float* __restrict__ bias,
                            float* __restrict__ out) {
    int bid = blockIdx.x;
    if (bid < 216) {
        int t = bid * 256 + threadIdx.x;
        ((float4*)g_aggF)[t] = make_float4(0.f, 0.f, 0.f, 0.f);
    } else if (bid < 648) {
        int i = (bid - 216) * 256 + threadIdx.x;   // 0..110591
        int n  = i & 127;
        int k2 = (i >> 7) & 31;
        int o  = i >> 12;                          // 0..26
        float w0 = weight[(o * CIN + 2 * k2) * COUT + n];
        float w1 = weight[(o * CIN + 2 * k2 + 1) * COUT + n];
        // SW128 swizzle: chunk bits[6:4] ^= (n&7)
        uint32_t off = (uint32_t)n * 128 + (((uint32_t)k2 * 4) ^ (((uint32_t)n & 7) << 4));
        *(uint32_t*)(g_Wn + (size_t)o * 16384 + off) = pack_h(w0, w1);
    } else {
        int i = (bid - 648) * 256 + threadIdx.x;   // float4 idx < OUTN/4 = 131072
        ((float4*)out)[i] = ((const float4*)bias)[i & 31];
    }
}

// ---------------------------------------------------------------------------
// Kernel 2: scatter-add features into per-voxel bins
// ---------------------------------------------------------------------------
__global__ void aggregate_kernel(const float* __restrict__ points,
                                 const float* __restrict__ feats) {
    int gid = blockIdx.x * blockDim.x + threadIdx.x;
    if (gid >= BATCH * NPTS * CIN) return;
    int c = gid & (CIN - 1);
    int p = gid >> 6;
    int b = p / NPTS;
    int vx = (int)points[p * 3 + 0];
    int vy = (int)points[p * 3 + 1];
    int vz = (int)points[p * 3 + 2];
    if ((unsigned)vx >= GRIDV || (unsigned)vy >= GRIDV || (unsigned)vz >= GRIDV) return;
    int lin = (vx * GRIDV + vy) * GRIDV + vz;
    atomicAdd(&g_aggF[(b * NVOX + lin) * CIN + c], feats[gid]);
}

// ---------------------------------------------------------------------------
// Kernel 3: convert aggF -> fp16 rows (once per voxel), plus zero row
// ---------------------------------------------------------------------------
__global__ void convert_kernel() {
    int gid = blockIdx.x * blockDim.x + threadIdx.x;
    if (gid >= (NROWS + 1) * 32) return;
    int row = gid >> 5;
    int c2  = gid & 31;
    uint32_t hp = 0;
    if (row < NROWS) {
        float2 v = *(const float2*)(g_aggF + (size_t)row * CIN + c2 * 2);
        hp = pack_h(v.x, v.y);
    }
    *(uint32_t*)(g_aggH + (size_t)row * 128 + c2 * 4) = hp;
}

// ---------------------------------------------------------------------------
// Kernel 4: split-K fp16 1-pass mma conv. grid = NTILE*NGRP = 192, 256 thr.
// Tile 64 points x 128 couts over offsets [g*9, +9).
// Warp (wm 0..3, wn 0..1): 16 rows x 64 couts. Epilogue atomicAdd into out.
// ---------------------------------------------------------------------------
#define RSTR   144
#define WBUF   16384                   // per-offset W (fp16)
#define ABUF   (TM * RSTR)             // 9216
#define SMO_W  0
#define SMO_A  (2 * WBUF)              // 32768
#define SMO_VOX (SMO_A + 2 * ABUF)     // 51200
#define SMO_MBAR (SMO_VOX + 3 * TM * 4)  // 51968
#define SMEM_TOTAL (SMO_MBAR + 64)     // 52032

__global__ __launch_bounds__(256, 2)
void conv_mma_kernel(const float* __restrict__ points, float* __restrict__ out) {
    extern __shared__ __align__(1024) unsigned char smem[];
    int* svox = (int*)(smem + SMO_VOX);

    const int tid  = threadIdx.x;
    const int warp = tid >> 5;
    const int lane = tid & 31;
    const int wm   = warp >> 1;      // 0..3 : rows [wm*16, +16)
    const int wn   = warp & 1;       // 0..1 : couts [wn*64, +64)
    const int grp  = lane >> 2;      // 0..7
    const int tig  = lane & 3;       // 0..3

    const int g    = blockIdx.x % NGRP;      // offset group
    const int tile = blockIdx.x / NGRP;      // point tile
    const int o0   = g * OPG;
    const int p0   = tile * TM;
    const int b    = p0 >> 11;       // / NPTS

    if (tid < TM) {
        int p = p0 + tid;
        svox[tid]          = (int)points[p * 3 + 0];
        svox[TM + tid]     = (int)points[p * 3 + 1];
        svox[2 * TM + tid] = (int)points[p * 3 + 2];
    }
    __syncthreads();

    const uint32_t sb = smem_u32(smem);
    const uint32_t mbar0 = sb + SMO_MBAR;
    const uint32_t mbar1 = sb + SMO_MBAR + 8;

    if (tid == 0) {
        MBAR_INIT(mbar0, 1);
        MBAR_INIT(mbar1, 1);
    }
    __syncthreads();

    // ---- A staging: 2 cp.async per thread (row = tid>>2, quarter = tid&3) ----
    const int arow = tid >> 2;           // 0..63
    const int aq   = tid & 3;            // 0..3 -> bytes [aq*32, +32)
    const int avx = svox[arow], avy = svox[TM + arow], avz = svox[2 * TM + arow];

    auto issueA = [&](int o, int bi) {
        int dx = o / 9 - 1, dy = (o / 3) % 3 - 1, dz = o % 3 - 1;
        int nx = avx + dx, ny = avy + dy, nz = avz + dz;
        int rowIdx = ZROW;
        if ((unsigned)nx < GRIDV && (unsigned)ny < GRIDV && (unsigned)nz < GRIDV)
            rowIdx = b * NVOX + (nx * GRIDV + ny) * GRIDV + nz;
        const unsigned char* srcH = g_aggH + (size_t)rowIdx * 128 + aq * 32;
        uint32_t dstH = sb + SMO_A + bi * ABUF + arow * RSTR + aq * 32;
        CP_ASYNC16(dstH,      srcH);
        CP_ASYNC16(dstH + 16, srcH + 16);
    };

    float c[32];
    #pragma unroll
    for (int i = 0; i < 32; i++) c[i] = 0.f;

    // ---- prologue: W0 bulk + A0 ----
    if (tid == 0) {
        MBAR_EXPECT_TX(mbar0, WBUF);
        BULK_G2S(sb + SMO_W, g_Wn + (size_t)o0 * WBUF, WBUF, mbar0);
    }
    issueA(o0, 0);
    CP_ASYNC_COMMIT();
    mbar_wait_parity(mbar0, 0);
    CP_ASYNC_WAIT0();
    __syncthreads();
    uint32_t ph0 = 1, ph1 = 0;   // next expected parity per buffer

    // ---- ldmatrix lane addressing ----
    // A (144B rows, no swizzle)
    const uint32_t aAddrBase = sb + SMO_A
        + (uint32_t)(wm * 16 + ((lane >> 3) & 1) * 8 + (lane & 7)) * RSTR
        + ((lane >> 4) & 1) * 16;
    // B (128B rows, SW128)
    const int bc   = lane & 7;
    const uint32_t bXor = (uint32_t)bc << 4;
    const uint32_t bRow0 = sb + SMO_W
        + (uint32_t)(wn * 64 + ((lane >> 4) & 1) * 8 + bc) * 128;
    const uint32_t bKsel = ((lane >> 3) & 1) * 16;

    for (int oo = 0; oo < OPG; oo++) {
        const int cur = oo & 1;
        const int nxt = cur ^ 1;
        const bool more = (oo + 1 < OPG);

        if (more) {
            if (tid == 0) {
                uint32_t mb = nxt ? mbar1 : mbar0;
                MBAR_EXPECT_TX(mb, WBUF);
                BULK_G2S(sb + SMO_W + nxt * WBUF,
                         g_Wn + (size_t)(o0 + oo + 1) * WBUF, WBUF, mb);
            }
            issueA(o0 + oo + 1, nxt);
            CP_ASYNC_COMMIT();
        }

        // ---- 1-pass mma over 4 k-steps ----
        const uint32_t aH = aAddrBase + (uint32_t)cur * ABUF;
        const uint32_t bB = bRow0 + (uint32_t)cur * WBUF;
        #pragma unroll
        for (int kk = 0; kk < 4; kk++) {
            const uint32_t kx = ((uint32_t)(kk * 32) + bKsel) ^ bXor;
            uint32_t ah[4];
            ldsm_x4(ah, aH + kk * 32);
            #pragma unroll
            for (int j = 0; j < 4; j++) {
                uint32_t bh[4];
                ldsm_x4(bh, bB + j * 2048 + kx);
                mma_f16(&c[(2 * j) * 4],     ah, bh[0], bh[1]);
                mma_f16(&c[(2 * j + 1) * 4], ah, bh[2], bh[3]);
            }
        }

        if (more) {
            if (nxt == 0) { mbar_wait_parity(mbar0, ph0); ph0 ^= 1; }
            else         { mbar_wait_parity(mbar1, ph1); ph1 ^= 1; }
            CP_ASYNC_WAIT0();
        }
        __syncthreads();
    }

    // ---- epilogue: atomicAdd partial into bias-initialized out ----
    const int r0 = p0 + wm * 16 + grp;
    #pragma unroll
    for (int f = 0; f < 8; f++) {
        int col = wn * 64 + f * 8 + tig * 2;
        const float* cc = &c[f * 4];
        float* oA = out + (size_t)r0 * COUT + col;
        float* oB = out + (size_t)(r0 + 8) * COUT + col;
        atomicAdd(oA,     cc[0]);
        atomicAdd(oA + 1, cc[1]);
        atomicAdd(oB,     cc[2]);
        atomicAdd(oB + 1, cc[3]);
    }
}

// ---------------------------------------------------------------------------
extern "C" void kernel_launch(void* const* d_in, const int* in_sizes, int n_in,
                              void* d_out, int out_size) {
    const float* points  = (const float*)d_in[0];   // (B, N, 3)
    const float* feats   = (const float*)d_in[1];   // (B, N, CIN)
    const float* weight  = (const float*)d_in[2];   // (3,3,3,CIN,COUT)
    const float* bias    = (const float*)d_in[3];   // (COUT)
    float* out = (float*)d_out;                     // (B, N, COUT)

    cudaFuncSetAttribute(conv_mma_kernel,
                         cudaFuncAttributeMaxDynamicSharedMemorySize, SMEM_TOTAL);

    // 1) zero agg scratch + pack W (fp16 swizzled) + out = bias
    prep_kernel<<<1160, 256>>>(weight, bias, out);
    // 2) per-voxel feature aggregation (fp32 atomics)
    aggregate_kernel<<<(BATCH * NPTS * CIN + 255) / 256, 256>>>(points, feats);
    // 3) convert aggF to fp16 rows (+ zero row)
    convert_kernel<<<((NROWS + 1) * 32 + 255) / 256, 256>>>();
    // 4) split-K fp16 1-pass conv, atomic accumulation into out
    conv_mma_kernel<<<NTILE * NGRP, 256, SMEM_TOTAL>>>(points, out);
}